// round 12
// baseline (speedup 1.0000x reference)
#include <cuda_runtime.h>
#include <math.h>

#define HH 96
#define WW 96
#define NSAMP 8
#define NT 768            // threads per block (load phase) — best-measured config
#define LD_PER 12         // 9216 / 768
#define EMPTY_T2 100000000  // sentinel: d^2 >= this means "target set empty"
#define FIXSCALE 1048576.0f // 2^20 fixed-point scale for the packed sum

// packed cross-block accumulator: [63:56] arrival count, [55:0] fixed-point sum
__device__ unsigned long long g_acc;

// nearest set-bit distance in a 96-bit row mask from position x (clamped 10000)
__device__ __forceinline__ int nearestDist(unsigned w0, unsigned w1, unsigned w2, int x) {
    int k = x >> 5, b = x & 31;
    unsigned lm = (2u << b) - 1u;
    unsigned hm = ~0u << b;
    unsigned c0 = (k == 0) ? (w0 & lm) : w0;
    unsigned c1 = (k == 0) ? 0u : ((k == 1) ? (w1 & lm) : w1);
    unsigned c2 = (k == 2) ? (w2 & lm) : 0u;
    int h = c2 ? (95 - __clz(c2))
          : (c1 ? (63 - __clz(c1))
          : (c0 ? (31 - __clz(c0)) : -20000));
    unsigned d0 = (k == 0) ? (w0 & hm) : 0u;
    unsigned d1 = (k == 0) ? w1 : ((k == 1) ? (w1 & hm) : 0u);
    unsigned d2 = (k == 2) ? (w2 & hm) : w2;
    int l = d0 ? (__ffs(d0) - 1)
          : (d1 ? (31 + __ffs(d1))
          : (d2 ? (63 + __ffs(d2)) : 20000));
    return min(min(x - h, l - x), 10000);
}

// OR into (c0,c1,c2) the 96-bit target row shifted by +dx and -dx (dx <= 31)
__device__ __forceinline__ void accum(unsigned& c0, unsigned& c1, unsigned& c2,
                                      const unsigned* t, int dx) {
    unsigned t0 = t[0], t1 = t[1], t2 = t[2];
    if (dx == 0) { c0 |= t0; c1 |= t1; c2 |= t2; return; }
    c0 |= t0 << dx;
    c1 |= __funnelshift_l(t0, t1, dx);
    c2 |= __funnelshift_l(t1, t2, dx);
    c2 |= t2 >> dx;
    c1 |= __funnelshift_r(t1, t2, dx);
    c0 |= __funnelshift_r(t0, t1, dx);
}

__global__ void __launch_bounds__(NT, 1)
haus_fused(const float* __restrict__ pred, const float* __restrict__ tgt,
           float* __restrict__ out) {
    const int n   = blockIdx.x;     // sample
    const int tid = threadIdx.x;

    __shared__ unsigned mA[HH][3];
    __shared__ unsigned mB[HH][3];
    __shared__ int s_wmax[6];

    const float* p = pred + n * (HH * WW);
    const float* t = tgt  + n * (HH * WW);

    // ---- prefetch all global data (MLP=24) ----
    float pv[LD_PER], tv[LD_PER];
#pragma unroll
    for (int k = 0; k < LD_PER; ++k) {
        pv[k] = p[tid + NT * k];
        tv[k] = t[tid + NT * k];
    }
    // ---- ballot into bitmasks (round_half_even(v) > 0.5  <=>  v > 0.5) ----
#pragma unroll
    for (int k = 0; k < LD_PER; ++k) {
        int i = tid + NT * k;
        unsigned wa = __ballot_sync(0xffffffffu, pv[k] > 0.5f);
        unsigned wb = __ballot_sync(0xffffffffu, tv[k] > 0.5f);
        if ((tid & 31) == 0) {
            int r = i / WW, ws = (i % WW) >> 5;
            mA[r][ws] = wa; mB[r][ws] = wb;
        }
    }
    __syncthreads();

    // ---- per-row dilation: warps 0-2 = dir 0 (src=A\B, tgt=B); warps 3-5 = dir 1 ----
    if (tid < 192) {
        const int dir = tid >= 96;
        const int r   = tid - dir * 96;
        const unsigned (*S)[3]  = dir ? mB : mA;   // src mask
        const unsigned (*Tg)[3] = dir ? mA : mB;   // tgt mask
        unsigned r0 = S[r][0] & ~Tg[r][0];
        unsigned r1 = S[r][1] & ~Tg[r][1];
        unsigned r2 = S[r][2] & ~Tg[r][2];

        int ans;
        if (!(r0 | r1 | r2)) {
            ans = -1;                    // no source points in this row
        } else {
            ans = 0;
            // compile-time offset table: all (dy,dx) with T=dy^2+dx^2 <= 32,
            // ascending T, 'last' marks end of each equal-T group.
            static const signed char EDY[30]  = {0,1, 1, 0,2, 1,2, 2, 0,3, 1,3, 2,3, 0,4, 1,4, 3, 2,4, 0,5,3,4, 1,5, 2,5, 4};
            static const signed char EDX[30]  = {1,0, 1, 2,0, 2,1, 2, 3,0, 3,1, 3,2, 4,0, 4,1, 3, 4,2, 5,0,4,3, 5,1, 5,2, 4};
            static const signed char ET [30]  = {1,1, 2, 4,4, 5,5, 8, 9,9, 10,10, 13,13, 16,16, 17,17, 18, 20,20, 25,25,25,25, 26,26, 29,29, 32};
            static const signed char ELAST[30]= {0,1, 1, 0,1, 0,1, 1, 0,1, 0,1,  0,1,  0,1,  0,1,  1,  0,1,  0,0,0,1,  0,1,  0,1,  1};
#pragma unroll
            for (int e = 0; e < 30; ++e) {
                const int dy = EDY[e], dx = EDX[e];
                unsigned c0 = 0, c1 = 0, c2 = 0;
                int ra = r - dy;
                if (ra >= 0) accum(c0, c1, c2, Tg[ra], dx);
                if (dy) {
                    int rb = r + dy;
                    if (rb < HH) accum(c0, c1, c2, Tg[rb], dx);
                }
                r0 &= ~c0; r1 &= ~c1; r2 &= ~c2;
                if (ELAST[e] && !(r0 | r1 | r2)) { ans = ET[e]; goto rowdone; }
            }
            // fallback: surviving points have d^2 > 32 (exact search; also
            // handles the empty-target case via the 10000 sentinel -> 1e8)
            for (int wb = 0; wb < 3; ++wb) {
                unsigned w = (wb == 0) ? r0 : ((wb == 1) ? r1 : r2);
                while (w) {
                    int x = wb * 32 + (__ffs(w) - 1);
                    w &= w - 1;
                    int best = 1 << 30;
                    for (int off = 0; off < HH; ++off) {
                        int dy2 = off * off;
                        if (dy2 >= best) break;
                        int ra = r - off;
                        if (ra >= 0) {
                            int v = nearestDist(Tg[ra][0], Tg[ra][1], Tg[ra][2], x);
                            best = min(best, dy2 + v * v);
                        }
                        int rb = r + off;
                        if (off && rb < HH) {
                            int v = nearestDist(Tg[rb][0], Tg[rb][1], Tg[rb][2], x);
                            best = min(best, dy2 + v * v);
                        }
                    }
                    ans = max(ans, best);
                }
            }
            rowdone: ;
        }

        int wmax = __reduce_max_sync(0xffffffffu, ans);
        if ((tid & 31) == 0) s_wmax[tid >> 5] = wmax;
    }
    __syncthreads();

    // ---- tail: tid0 only. Single packed 64-bit atomic carries BOTH the
    //      arrival count (bits 63:56) and the fixed-point sum (bits 55:0).
    //      Integer adds are order-independent -> deterministic result. ----
    if (tid == 0) {
        int m0 = max(s_wmax[0], max(s_wmax[1], s_wmax[2]));
        int m1 = max(s_wmax[3], max(s_wmax[4], s_wmax[5]));
        float d0 = (m0 < 0) ? 0.0f : ((m0 >= EMPTY_T2) ? 1e9f : sqrtf((float)m0) * (1.0f / 96.0f));
        float d1 = (m1 < 0) ? 0.0f : ((m1 >= EMPTY_T2) ? 1e9f : sqrtf((float)m1) * (1.0f / 96.0f));
        float dist = fmaxf(d0, d1);
        unsigned long long contrib = (1ULL << 56) + __float2ull_rn(dist * FIXSCALE);
        unsigned long long old;
        asm volatile("atom.acq_rel.gpu.global.add.u64 %0, [%1], %2;"
                     : "=l"(old) : "l"(&g_acc), "l"(contrib) : "memory");
        if ((old >> 56) == NSAMP - 1) {
            // winner: final sum is already in hand — no extra memory round trip
            unsigned long long total = (old + contrib) & ((1ULL << 56) - 1ULL);
            out[0] = (float)((double)total) * (1.0f / (NSAMP * FIXSCALE));
            *(volatile unsigned long long*)&g_acc = 0ULL;  // reset for next replay
        }
    }
}

extern "C" void kernel_launch(void* const* d_in, const int* in_sizes, int n_in,
                              void* d_out, int out_size) {
    const float* pred = (const float*)d_in[0];
    const float* tgt  = (const float*)d_in[1];
    haus_fused<<<NSAMP, NT>>>(pred, tgt, (float*)d_out);
}

// round 14
// speedup vs baseline: 1.0294x; 1.0294x over previous
#include <cuda_runtime.h>
#include <math.h>

#define HH 96
#define WW 96
#define NSAMP 8
#define NT 768            // threads per block (load phase)
#define LD_PER 12         // 9216 / 768
#define EMPTY_T2 100000000  // sentinel: d^2 >= this means "target set empty"

// cross-block scratch
__device__ float g_part[NSAMP];
__device__ int   g_count;

// nearest set-bit distance in a 96-bit row mask from position x (clamped 10000)
__device__ __forceinline__ int nearestDist(unsigned w0, unsigned w1, unsigned w2, int x) {
    int k = x >> 5, b = x & 31;
    unsigned lm = (2u << b) - 1u;
    unsigned hm = ~0u << b;
    unsigned c0 = (k == 0) ? (w0 & lm) : w0;
    unsigned c1 = (k == 0) ? 0u : ((k == 1) ? (w1 & lm) : w1);
    unsigned c2 = (k == 2) ? (w2 & lm) : 0u;
    int h = c2 ? (95 - __clz(c2))
          : (c1 ? (63 - __clz(c1))
          : (c0 ? (31 - __clz(c0)) : -20000));
    unsigned d0 = (k == 0) ? (w0 & hm) : 0u;
    unsigned d1 = (k == 0) ? w1 : ((k == 1) ? (w1 & hm) : 0u);
    unsigned d2 = (k == 2) ? (w2 & hm) : w2;
    int l = d0 ? (__ffs(d0) - 1)
          : (d1 ? (31 + __ffs(d1))
          : (d2 ? (63 + __ffs(d2)) : 20000));
    return min(min(x - h, l - x), 10000);
}

// OR into (c0,c1,c2) the 96-bit target row shifted by +dx and -dx (dx <= 31)
__device__ __forceinline__ void accum(unsigned& c0, unsigned& c1, unsigned& c2,
                                      const unsigned* t, int dx) {
    unsigned t0 = t[0], t1 = t[1], t2 = t[2];
    if (dx == 0) { c0 |= t0; c1 |= t1; c2 |= t2; return; }
    c0 |= t0 << dx;
    c1 |= __funnelshift_l(t0, t1, dx);
    c2 |= __funnelshift_l(t1, t2, dx);
    c2 |= t2 >> dx;
    c1 |= __funnelshift_r(t1, t2, dx);
    c0 |= __funnelshift_r(t0, t1, dx);
}

__global__ void __launch_bounds__(NT, 1)
haus_fused(const float* __restrict__ pred, const float* __restrict__ tgt,
           float* __restrict__ out) {
    const int n   = blockIdx.x;     // sample
    const int tid = threadIdx.x;

    __shared__ unsigned mA[HH][3];
    __shared__ unsigned mB[HH][3];
    __shared__ int s_wmax[6];

    const float* p = pred + n * (HH * WW);
    const float* t = tgt  + n * (HH * WW);

    // ---- prefetch all global data (MLP=24) ----
    float pv[LD_PER], tv[LD_PER];
#pragma unroll
    for (int k = 0; k < LD_PER; ++k) {
        pv[k] = p[tid + NT * k];
        tv[k] = t[tid + NT * k];
    }
    // ---- ballot into bitmasks (round_half_even(v) > 0.5  <=>  v > 0.5) ----
#pragma unroll
    for (int k = 0; k < LD_PER; ++k) {
        int i = tid + NT * k;
        unsigned wa = __ballot_sync(0xffffffffu, pv[k] > 0.5f);
        unsigned wb = __ballot_sync(0xffffffffu, tv[k] > 0.5f);
        if ((tid & 31) == 0) {
            int r = i / WW, ws = (i % WW) >> 5;
            mA[r][ws] = wa; mB[r][ws] = wb;
        }
    }
    __syncthreads();

    // ---- per-row dilation: warps 0-2 = dir 0 (src=A\B, tgt=B); warps 3-5 = dir 1 ----
    if (tid < 192) {
        const int dir = tid >= 96;
        const int r   = tid - dir * 96;
        const unsigned (*S)[3]  = dir ? mB : mA;   // src mask
        const unsigned (*Tg)[3] = dir ? mA : mB;   // tgt mask
        unsigned r0 = S[r][0] & ~Tg[r][0];
        unsigned r1 = S[r][1] & ~Tg[r][1];
        unsigned r2 = S[r][2] & ~Tg[r][2];

        int ans;
        if (!(r0 | r1 | r2)) {
            ans = -1;                    // no source points in this row
        } else {
            ans = 0;
            // compile-time offset table: all (dy,dx) with T=dy^2+dx^2 <= 32,
            // ascending T, 'last' marks end of each equal-T group.
            static const signed char EDY[30]  = {0,1, 1, 0,2, 1,2, 2, 0,3, 1,3, 2,3, 0,4, 1,4, 3, 2,4, 0,5,3,4, 1,5, 2,5, 4};
            static const signed char EDX[30]  = {1,0, 1, 2,0, 2,1, 2, 3,0, 3,1, 3,2, 4,0, 4,1, 3, 4,2, 5,0,4,3, 5,1, 5,2, 4};
            static const signed char ET [30]  = {1,1, 2, 4,4, 5,5, 8, 9,9, 10,10, 13,13, 16,16, 17,17, 18, 20,20, 25,25,25,25, 26,26, 29,29, 32};
            static const signed char ELAST[30]= {0,1, 1, 0,1, 0,1, 1, 0,1, 0,1,  0,1,  0,1,  0,1,  1,  0,1,  0,0,0,1,  0,1,  0,1,  1};
#pragma unroll
            for (int e = 0; e < 30; ++e) {
                const int dy = EDY[e], dx = EDX[e];
                unsigned c0 = 0, c1 = 0, c2 = 0;
                int ra = r - dy;
                if (ra >= 0) accum(c0, c1, c2, Tg[ra], dx);
                if (dy) {
                    int rb = r + dy;
                    if (rb < HH) accum(c0, c1, c2, Tg[rb], dx);
                }
                r0 &= ~c0; r1 &= ~c1; r2 &= ~c2;
                if (ELAST[e] && !(r0 | r1 | r2)) { ans = ET[e]; goto rowdone; }
            }
            // fallback: surviving points have d^2 > 32 (exact search; also
            // handles the empty-target case via the 10000 sentinel -> 1e8)
            for (int wb = 0; wb < 3; ++wb) {
                unsigned w = (wb == 0) ? r0 : ((wb == 1) ? r1 : r2);
                while (w) {
                    int x = wb * 32 + (__ffs(w) - 1);
                    w &= w - 1;
                    int best = 1 << 30;
                    for (int off = 0; off < HH; ++off) {
                        int dy2 = off * off;
                        if (dy2 >= best) break;
                        int ra = r - off;
                        if (ra >= 0) {
                            int v = nearestDist(Tg[ra][0], Tg[ra][1], Tg[ra][2], x);
                            best = min(best, dy2 + v * v);
                        }
                        int rb = r + off;
                        if (off && rb < HH) {
                            int v = nearestDist(Tg[rb][0], Tg[rb][1], Tg[rb][2], x);
                            best = min(best, dy2 + v * v);
                        }
                    }
                    ans = max(ans, best);
                }
            }
            rowdone: ;
        }

        int wmax = __reduce_max_sync(0xffffffffu, ans);
        if ((tid & 31) == 0) s_wmax[tid >> 5] = wmax;
    }
    __syncthreads();

    // ---- tail: tid0 only; no further block-wide sync needed ----
    if (tid == 0) {
        int m0 = max(s_wmax[0], max(s_wmax[1], s_wmax[2]));
        int m1 = max(s_wmax[3], max(s_wmax[4], s_wmax[5]));
        float d0 = (m0 < 0) ? 0.0f : ((m0 >= EMPTY_T2) ? 1e9f : sqrtf((float)m0) * (1.0f / 96.0f));
        float d1 = (m1 < 0) ? 0.0f : ((m1 >= EMPTY_T2) ? 1e9f : sqrtf((float)m1) * (1.0f / 96.0f));
        g_part[n] = fmaxf(d0, d1);
        // acq_rel atomic: release publishes g_part[n]; acquire in the winner
        // synchronizes with all other blocks' releases.
        int old;
        asm volatile("atom.acq_rel.gpu.global.add.s32 %0, [%1], %2;"
                     : "=r"(old) : "l"(&g_count), "r"(1) : "memory");
        if (old == NSAMP - 1) {
            // winner: 8 independent L2 loads (one round-trip), fixed-order sum
            float s = 0.0f;
#pragma unroll
            for (int i = 0; i < NSAMP; ++i) s += __ldcg(&g_part[i]);
            out[0] = s * (1.0f / NSAMP);
            g_count = 0;   // reset for next graph replay (stream-ordered)
        }
    }
}

extern "C" void kernel_launch(void* const* d_in, const int* in_sizes, int n_in,
                              void* d_out, int out_size) {
    const float* pred = (const float*)d_in[0];
    const float* tgt  = (const float*)d_in[1];
    haus_fused<<<NSAMP, NT>>>(pred, tgt, (float*)d_out);
}